// round 11
// baseline (speedup 1.0000x reference)
#include <cuda_runtime.h>
#include <cuda_fp16.h>

typedef unsigned long long u64;
typedef unsigned int u32;

#define HW_   56
#define CIN_  256
#define OC_   256
#define NIMG  32

// SMEM layout (dynamic)
#define SA_STR  48                 // A row stride bytes (16 halves = 32B data + 16B pad)
#define SM_AHI  0                  // 260 rows * 48 = 12480
#define SM_ALO  12480              // 12480
#define SM_B    24960              // 9 taps * 2 splits * 128 oc * 16 k * 2B = 73728
#define SM_BIAS 98688              // 512
#define SM_TOT  99328
// Epilogue reuses [0, 66560) as C: [128 oc][130 px] f32

// Pre-packed fp16-split weights:
// index = ((((ch*9+tap)*2+split)*2+half)*128 + ocl)*16 + k
__device__ __align__(16) __half g_wh[16 * 9 * 2 * 2 * 128 * 16];

__device__ __forceinline__ u32 smem_u32(const void* p) {
    u32 a;
    asm("{ .reg .u64 t; cvta.to.shared.u64 t, %1; cvt.u32.u64 %0, t; }"
        : "=r"(a) : "l"(p));
    return a;
}
__device__ __forceinline__ void ldsm4(u32& r0, u32& r1, u32& r2, u32& r3, u32 addr) {
    asm volatile("ldmatrix.sync.aligned.m8n8.x4.shared.b16 {%0,%1,%2,%3}, [%4];"
                 : "=r"(r0), "=r"(r1), "=r"(r2), "=r"(r3) : "r"(addr));
}
__device__ __forceinline__ void mma16816(float* c, u32 a0, u32 a1, u32 a2, u32 a3,
                                         u32 b0, u32 b1) {
    asm volatile(
        "mma.sync.aligned.m16n8k16.row.col.f32.f16.f16.f32 "
        "{%0,%1,%2,%3}, {%4,%5,%6,%7}, {%8,%9}, {%0,%1,%2,%3};"
        : "+f"(c[0]), "+f"(c[1]), "+f"(c[2]), "+f"(c[3])
        : "r"(a0), "r"(a1), "r"(a2), "r"(a3), "r"(b0), "r"(b1));
}

// ---------------------------------------------------------------------------
// Kernel A: dequantize + fp16 hi/lo split + pack into per-chunk B tiles.
// ---------------------------------------------------------------------------
__global__ void dequant_wh(const int* __restrict__ q,
                           const float* __restrict__ sc,
                           const float* __restrict__ mn) {
    int i = blockIdx.x * 256 + threadIdx.x;
    if (i >= 16 * 9 * 2 * 2 * 128 * 16) return;
    float s = *sc, m = *mn;
    int ch = i / 73728, r = i % 73728;
    int tap = r / 8192, r2 = r % 8192;
    int split = r2 / 4096, r3 = r2 % 4096;
    int hf = r3 / 2048, r4 = r3 % 2048;
    int ocl = r4 / 16, k = r4 % 16;
    int oc = hf * 128 + ocl, cin = ch * 16 + k;
    float w = (float)q[(oc * CIN_ + cin) * 9 + tap] * s + m;
    __half h = __float2half(w);
    g_wh[i] = (split == 0) ? h : __float2half(w - __half2float(h));
}

// ---------------------------------------------------------------------------
// Kernel B: implicit conv via warp-level HMMA (m16n8k16 fp16, fp32 acc).
// grid = (2 oc-halves, 28 row-pairs, 32 imgs), block = 256 threads (8 warps).
// CTA tile: M=128 px (2 rows x 64-pitch) x N=128 oc. Warp tile 64x32.
// K per chunk-tap = 16 cin; taps = A row shifts; 3 split-product terms.
// ---------------------------------------------------------------------------
extern __shared__ char smem[];
__global__ void __launch_bounds__(256, 1)
conv_hmma(const float* __restrict__ x,
          const float* __restrict__ bias,
          float* __restrict__ out) {
    const u32 sb32 = smem_u32(smem);
    const int tid = threadIdx.x, wid = tid >> 5, lane = tid & 31;
    const int half_ = blockIdx.x, rp = blockIdx.y, n = blockIdx.z;
    const int r0 = rp * 2, oc0 = half_ * 128;
    const int warp_m = wid & 1, warp_n = wid >> 1;

    float* s_bias = (float*)(smem + SM_BIAS);
    if (tid < 128) s_bias[tid] = bias[oc0 + tid];

    float acc[4][4][4];
#pragma unroll
    for (int a = 0; a < 4; a++)
#pragma unroll
        for (int b = 0; b < 4; b++)
#pragma unroll
            for (int c = 0; c < 4; c++) acc[a][b][c] = 0.0f;

    const float* xn = x + (u64)n * CIN_ * HW_ * HW_;

    // ldmatrix lane address components
    const int a_row = lane & 15, a_seg = lane >> 4;
    const int b_row = (lane & 7) + ((lane >> 4) << 3), b_seg = (lane >> 3) & 1;
    const u32 sa_hi = sb32 + SM_AHI, sa_lo = sb32 + SM_ALO, sbB = sb32 + SM_B;

    for (int ch = 0; ch < 16; ch++) {
        // ---- stage A: 260 rows x 16 cin, fp16 hi/lo, zero-padded halo ----
        for (int i = tid; i < 260 * 16; i += 256) {
            int qs = i % 260, ck = i / 260;
            int g = (r0 - 1) * 64 + qs - 1;          // virtual 64-pitch pixel idx
            float v = 0.0f;
            if (g >= 0) {
                int row = g >> 6, iw = g & 63;
                if (row < HW_ && iw < HW_)
                    v = xn[(u64)(ch * 16 + ck) * (HW_ * HW_) + row * HW_ + iw];
            }
            __half h = __float2half(v);
            __half l = __float2half(v - __half2float(h));
            *(__half*)(smem + SM_AHI + qs * SA_STR + ck * 2) = h;
            *(__half*)(smem + SM_ALO + qs * SA_STR + ck * 2) = l;
        }
        // ---- stage B: 18 tiles (9 taps x 2 splits) of 4096B, straight copy ----
        for (int t = 0; t < 18; t++) {
            int tap = t >> 1, split = t & 1;
            const float4* src = (const float4*)(g_wh +
                (u64)((((ch * 9 + tap) * 2 + split) * 2 + half_) * 2048));
            ((float4*)(smem + SM_B + t * 4096))[tid] = src[tid];
        }
        __syncthreads();

        // ---- compute ----
#pragma unroll 1
        for (int tap = 0; tap < 9; tap++) {
            const int kh = tap / 3, kw = tap - kh * 3;
            // B fragments: 4 n-tiles, hi & lo
            u32 bh[8], bl[8];
            u32 bb_h = sbB + (tap * 2 + 0) * 4096 + warp_n * 32 * 32;
            u32 bb_l = bb_h + 4096;
            ldsm4(bh[0], bh[1], bh[2], bh[3], bb_h + b_row * 32 + b_seg * 16);
            ldsm4(bh[4], bh[5], bh[6], bh[7], bb_h + (16 + b_row) * 32 + b_seg * 16);
            ldsm4(bl[0], bl[1], bl[2], bl[3], bb_l + b_row * 32 + b_seg * 16);
            ldsm4(bl[4], bl[5], bl[6], bl[7], bb_l + (16 + b_row) * 32 + b_seg * 16);

#pragma unroll
            for (int mt = 0; mt < 4; mt++) {
                int qs_base = warp_m * 64 + mt * 16 + kh * 64 + kw;
                u32 aoff = (u32)((qs_base + a_row) * SA_STR + a_seg * 16);
                u32 ah0, ah1, ah2, ah3, al0, al1, al2, al3;
                ldsm4(ah0, ah1, ah2, ah3, sa_hi + aoff);
                ldsm4(al0, al1, al2, al3, sa_lo + aoff);
#pragma unroll
                for (int nt = 0; nt < 4; nt++) {
                    mma16816(acc[mt][nt], ah0, ah1, ah2, ah3, bh[nt * 2], bh[nt * 2 + 1]);
                    mma16816(acc[mt][nt], ah0, ah1, ah2, ah3, bl[nt * 2], bl[nt * 2 + 1]);
                    mma16816(acc[mt][nt], al0, al1, al2, al3, bh[nt * 2], bh[nt * 2 + 1]);
                }
            }
        }
        __syncthreads();
    }

    // ---- epilogue: frags -> smem (transpose) -> coalesced gmem + bias ----
    float* sc = (float*)smem;     // [128 oc][130 px]
#pragma unroll
    for (int mt = 0; mt < 4; mt++)
#pragma unroll
        for (int nt = 0; nt < 4; nt++) {
            int px = warp_m * 64 + mt * 16 + (lane >> 2);
            int ocl = warp_n * 32 + nt * 8 + (lane & 3) * 2;
            sc[ocl * 130 + px]           = acc[mt][nt][0];
            sc[(ocl + 1) * 130 + px]     = acc[mt][nt][1];
            sc[ocl * 130 + px + 8]       = acc[mt][nt][2];
            sc[(ocl + 1) * 130 + px + 8] = acc[mt][nt][3];
        }
    __syncthreads();

    for (int i = tid; i < 128 * 112; i += 256) {
        int ocl = i / 112, p = i % 112;
        int orow = p / 56, ow = p % 56;
        int px = orow * 64 + ow;
        out[((u64)(n * OC_ + oc0 + ocl) * HW_ + (r0 + orow)) * HW_ + ow] =
            sc[ocl * 130 + px] + s_bias[ocl];
    }
}

// ---------------------------------------------------------------------------
// Launch: inputs: x, q_weight, w_scale, w_min, bias
// ---------------------------------------------------------------------------
extern "C" void kernel_launch(void* const* d_in, const int* in_sizes, int n_in,
                              void* d_out, int out_size) {
    const float* x    = (const float*)d_in[0];
    const int*   q    = (const int*)  d_in[1];
    const float* ws   = (const float*)d_in[2];
    const float* wm   = (const float*)d_in[3];
    const float* bias = (const float*)d_in[4];
    float* out = (float*)d_out;
    (void)in_sizes; (void)n_in; (void)out_size;

    cudaFuncSetAttribute(conv_hmma, cudaFuncAttributeMaxDynamicSharedMemorySize, SM_TOT);

    dequant_wh<<<(16 * 9 * 2 * 2 * 128 * 16 + 255) / 256, 256>>>(q, ws, wm);

    dim3 grid(2, 28, NIMG);
    conv_hmma<<<grid, 256, SM_TOT>>>(x, bias, out);
}

// round 13
// speedup vs baseline: 2.7039x; 2.7039x over previous
#include <cuda_runtime.h>
#include <cuda_fp16.h>

typedef unsigned long long u64;
typedef unsigned int u32;

#define HW_   56
#define CIN_  256
#define OC_   256
#define NIMG  32
#define NCH   16

// smem layout: two stages of (A_hi | A_lo | B), then bias
#define ST_A   13056               // 272 rows * 48B per A split
#define ST_B   55296               // 9 taps * 128 ocl * 48B
#define ST_SZ  (2 * ST_A + ST_B)   // 81408
#define SM_BIAS (2 * ST_SZ)        // 162816
#define SM_TOT  (SM_BIAS + 512)    // 163328
// epilogue reuses [0, 66560) as C[128 oc][130 px] f32

// fp16 weights (single precision level): [ch][tap][half][ocl][k16]
__device__ __align__(16) __half g_wh[NCH * 9 * 2 * 128 * 16];
// x pre-packed per (n, ch): [3840 padded pixels][16 ck] fp16 hi / lo
// pixel slab: 128 guard + 3584 (56 rows * 64 pitch) + 128 guard
__device__ __align__(16) __half g_xh[(u64)NIMG * NCH * 3840 * 16];
__device__ __align__(16) __half g_xl[(u64)NIMG * NCH * 3840 * 16];

__device__ __forceinline__ u32 smem_u32(const void* p) {
    u32 a;
    asm("{ .reg .u64 t; cvta.to.shared.u64 t, %1; cvt.u32.u64 %0, t; }"
        : "=r"(a) : "l"(p));
    return a;
}
__device__ __forceinline__ void ldsm4(u32& r0, u32& r1, u32& r2, u32& r3, u32 addr) {
    asm volatile("ldmatrix.sync.aligned.m8n8.x4.shared.b16 {%0,%1,%2,%3}, [%4];"
                 : "=r"(r0), "=r"(r1), "=r"(r2), "=r"(r3) : "r"(addr));
}
__device__ __forceinline__ void mma16816(float* c, u32 a0, u32 a1, u32 a2, u32 a3,
                                         u32 b0, u32 b1) {
    asm volatile(
        "mma.sync.aligned.m16n8k16.row.col.f32.f16.f16.f32 "
        "{%0,%1,%2,%3}, {%4,%5,%6,%7}, {%8,%9}, {%0,%1,%2,%3};"
        : "+f"(c[0]), "+f"(c[1]), "+f"(c[2]), "+f"(c[3])
        : "r"(a0), "r"(a1), "r"(a2), "r"(a3), "r"(b0), "r"(b1));
}
__device__ __forceinline__ void cpasync16(u32 dst, const void* src) {
    asm volatile("cp.async.cg.shared.global [%0], [%1], 16;"
                 :: "r"(dst), "l"(src) : "memory");
}

// ---------------------------------------------------------------------------
// Pre-pass 1: dequantize weights -> single fp16, packed [ch][tap][half][ocl][k]
// ---------------------------------------------------------------------------
__global__ void dequant_wh(const int* __restrict__ q,
                           const float* __restrict__ sc,
                           const float* __restrict__ mn) {
    int i = blockIdx.x * 256 + threadIdx.x;
    if (i >= NCH * 9 * 2 * 128 * 16) return;
    float s = *sc, m = *mn;
    int ch = i / 36864, r = i % 36864;
    int tap = r / 4096, r2 = r % 4096;
    int hf = r2 / 2048, r3 = r2 % 2048;
    int ocl = r3 / 16, k = r3 % 16;
    int oc = hf * 128 + ocl, cin = ch * 16 + k;
    g_wh[i] = __float2half((float)q[(oc * CIN_ + cin) * 9 + tap] * s + m);
}

// ---------------------------------------------------------------------------
// Pre-pass 2: x -> fp16 hi/lo, chunk-major padded 64-pitch slabs with guards.
// ---------------------------------------------------------------------------
__global__ void pack_x(const float* __restrict__ x) {
    u32 i = blockIdx.x * 256 + threadIdx.x;
    if (i >= (u32)NIMG * NCH * 3840) return;
    u32 pg = i % 3840, nc = i / 3840;       // nc = n*16 + ch
    int g = (int)pg - 128;
    int row = g >> 6, col = g & 63;
    bool ok = (g >= 0) && (row < HW_) && (col < HW_);
    __align__(16) __half hv[16];
    __align__(16) __half lv[16];
#pragma unroll
    for (int ck = 0; ck < 16; ck++) {
        float v = 0.0f;
        if (ok) v = x[((u64)nc * 16 + ck) * (HW_ * HW_) + row * HW_ + col];
        __half h = __float2half(v);
        hv[ck] = h;
        lv[ck] = __float2half(v - __half2float(h));
    }
    u64 o = ((u64)nc * 3840 + pg) * 16;
    *(uint4*)(g_xh + o)     = *(uint4*)hv;
    *(uint4*)(g_xh + o + 8) = *(uint4*)(hv + 8);
    *(uint4*)(g_xl + o)     = *(uint4*)lv;
    *(uint4*)(g_xl + o + 8) = *(uint4*)(lv + 8);
}

// ---------------------------------------------------------------------------
// Conv: HMMA implicit conv, 16 warps, cp.async double-buffered staging.
// grid = (2 oc-halves, 28 row-pairs, 32 imgs), block = 512.
// CTA tile M=128 px x N=128 oc; warp tile 32x32; K-chunk = 16 cin x 9 taps.
// ---------------------------------------------------------------------------
extern __shared__ char smem[];
__global__ void __launch_bounds__(512, 1)
conv_hmma(const float* __restrict__ bias, float* __restrict__ out) {
    const u32 sb = smem_u32(smem);
    const int tid = threadIdx.x, wid = tid >> 5, lane = tid & 31;
    const int half_ = blockIdx.x, rp = blockIdx.y, n = blockIdx.z;
    const int r0 = rp * 2, oc0 = half_ * 128;
    const int warp_m = wid & 3, warp_n = wid >> 2;

    float* s_bias = (float*)(smem + SM_BIAS);
    if (tid < 128) s_bias[tid] = bias[oc0 + tid];

    float acc[2][4][4];
#pragma unroll
    for (int a = 0; a < 2; a++)
#pragma unroll
        for (int b = 0; b < 4; b++)
#pragma unroll
            for (int c = 0; c < 4; c++) acc[a][b][c] = 0.0f;

    const u32 abase_pix = (u32)(r0 * 64 + 56);   // slab index of staged row 0
    const int a_row = lane & 15, a_seg = lane >> 4;
    const int b_row = (lane & 7) + ((lane >> 4) << 3), b_seg = (lane >> 3) & 1;

    auto prefetch = [&](int ch, int s) {
        u32 aH = sb + s * ST_SZ, aL = aH + ST_A, bB = aH + 2 * ST_A;
        const __half* srcH = g_xh + ((u64)(n * NCH + ch) * 3840 + abase_pix) * 16;
        const __half* srcL = g_xl + ((u64)(n * NCH + ch) * 3840 + abase_pix) * 16;
        for (int i = tid; i < 544; i += 512) {            // 272 rows x 2 halves
            int qs = i >> 1, h = i & 1;
            cpasync16(aH + qs * 48 + h * 16, srcH + qs * 16 + h * 8);
            cpasync16(aL + qs * 48 + h * 16, srcL + qs * 16 + h * 8);
        }
        for (int i = tid; i < 2304; i += 512) {           // 9 taps x 128 ocl x 2
            int tap = i / 256, r = i & 255, ocl = r >> 1, h = r & 1;
            const __half* sBp = g_wh +
                (u64)((ch * 9 + tap) * 2 + half_) * 2048 + ocl * 16 + h * 8;
            cpasync16(bB + tap * 6144 + ocl * 48 + h * 16, sBp);
        }
        asm volatile("cp.async.commit_group;" ::: "memory");
    };

    prefetch(0, 0);
    prefetch(1, 1);

    for (int ch = 0; ch < NCH; ch++) {
        const int s = ch & 1;
        if (ch == NCH - 1)
            asm volatile("cp.async.wait_group 0;" ::: "memory");
        else
            asm volatile("cp.async.wait_group 1;" ::: "memory");
        __syncthreads();

        const u32 aH = sb + s * ST_SZ, aL = aH + ST_A, bB = aH + 2 * ST_A;
#pragma unroll 1
        for (int tap = 0; tap < 9; tap++) {
            const int kh = tap / 3, kwp = tap - kh * 3 + 7;
            u32 bf[8];
            u32 bb = bB + tap * 6144 + warp_n * 1536;
            ldsm4(bf[0], bf[1], bf[2], bf[3], bb + b_row * 48 + b_seg * 16);
            ldsm4(bf[4], bf[5], bf[6], bf[7], bb + (16 + b_row) * 48 + b_seg * 16);
#pragma unroll
            for (int mt = 0; mt < 2; mt++) {
                int qs = warp_m * 32 + mt * 16 + kh * 64 + kwp + a_row;
                u32 ah0, ah1, ah2, ah3, al0, al1, al2, al3;
                ldsm4(ah0, ah1, ah2, ah3, aH + qs * 48 + a_seg * 16);
                ldsm4(al0, al1, al2, al3, aL + qs * 48 + a_seg * 16);
#pragma unroll
                for (int nt = 0; nt < 4; nt++) {
                    mma16816(acc[mt][nt], ah0, ah1, ah2, ah3, bf[nt * 2], bf[nt * 2 + 1]);
                    mma16816(acc[mt][nt], al0, al1, al2, al3, bf[nt * 2], bf[nt * 2 + 1]);
                }
            }
        }
        __syncthreads();
        if (ch + 2 < NCH) prefetch(ch + 2, s);
    }

    // epilogue: frags -> smem transpose -> coalesced gmem + bias
    float* scf = (float*)smem;     // [128 oc][130 px]
#pragma unroll
    for (int mt = 0; mt < 2; mt++)
#pragma unroll
        for (int nt = 0; nt < 4; nt++) {
            int px = warp_m * 32 + mt * 16 + (lane >> 2);
            int ocl = warp_n * 32 + nt * 8 + (lane & 3) * 2;
            scf[ocl * 130 + px]           = acc[mt][nt][0];
            scf[(ocl + 1) * 130 + px]     = acc[mt][nt][1];
            scf[ocl * 130 + px + 8]       = acc[mt][nt][2];
            scf[(ocl + 1) * 130 + px + 8] = acc[mt][nt][3];
        }
    __syncthreads();

    for (int i = tid; i < 128 * 112; i += 512) {
        int ocl = i / 112, p = i % 112;
        int orow = p / 56, ow = p % 56;
        int px = orow * 64 + ow;
        out[((u64)(n * OC_ + oc0 + ocl) * HW_ + (r0 + orow)) * HW_ + ow] =
            scf[ocl * 130 + px] + s_bias[ocl];
    }
}

// ---------------------------------------------------------------------------
// Launch: inputs: x, q_weight, w_scale, w_min, bias
// ---------------------------------------------------------------------------
extern "C" void kernel_launch(void* const* d_in, const int* in_sizes, int n_in,
                              void* d_out, int out_size) {
    const float* x    = (const float*)d_in[0];
    const int*   q    = (const int*)  d_in[1];
    const float* ws   = (const float*)d_in[2];
    const float* wm   = (const float*)d_in[3];
    const float* bias = (const float*)d_in[4];
    float* out = (float*)d_out;
    (void)in_sizes; (void)n_in; (void)out_size;

    cudaFuncSetAttribute(conv_hmma, cudaFuncAttributeMaxDynamicSharedMemorySize, SM_TOT);

    dequant_wh<<<(NCH * 9 * 2 * 128 * 16 + 255) / 256, 256>>>(q, ws, wm);
    pack_x<<<((u32)NIMG * NCH * 3840 + 255) / 256, 256>>>(x);

    dim3 grid(2, 28, NIMG);
    conv_hmma<<<grid, 512, SM_TOT>>>(bias, out);
}

// round 16
// speedup vs baseline: 3.9113x; 1.4466x over previous
#include <cuda_runtime.h>
#include <cuda_fp16.h>

typedef unsigned long long u64;
typedef unsigned int u32;

#define HW_   56
#define CIN_  256
#define OC_   256
#define NIMG  32
#define NCH   16

// smem: three stages of (A | B), then bias
#define ST_A   13056               // 272 rows * 48B
#define ST_B   55296               // 9 taps * 128 ocl * 48B
#define ST_SZ  (ST_A + ST_B)       // 68352
#define SM_BIAS (3 * ST_SZ)        // 205056
#define SM_TOT  (SM_BIAS + 512)    // 205568
// epilogue reuses [0, 66560) as C[128 oc][130 px] f32

// fp16 weights: [ch][tap][half][ocl][k16]
__device__ __align__(16) __half g_wh[NCH * 9 * 2 * 128 * 16];
// x packed fp16 per (n, ch): [3840 padded pixels][16 ck]
// pixel slab: 128 guard + 3584 (56 rows * 64 pitch) + 128 guard
__device__ __align__(16) __half g_xh[(u64)NIMG * NCH * 3840 * 16];

__device__ __forceinline__ u32 smem_u32(const void* p) {
    u32 a;
    asm("{ .reg .u64 t; cvta.to.shared.u64 t, %1; cvt.u32.u64 %0, t; }"
        : "=r"(a) : "l"(p));
    return a;
}
__device__ __forceinline__ void ldsm4(u32& r0, u32& r1, u32& r2, u32& r3, u32 addr) {
    asm volatile("ldmatrix.sync.aligned.m8n8.x4.shared.b16 {%0,%1,%2,%3}, [%4];"
                 : "=r"(r0), "=r"(r1), "=r"(r2), "=r"(r3) : "r"(addr));
}
__device__ __forceinline__ void mma16816(float* c, u32 a0, u32 a1, u32 a2, u32 a3,
                                         u32 b0, u32 b1) {
    asm volatile(
        "mma.sync.aligned.m16n8k16.row.col.f32.f16.f16.f32 "
        "{%0,%1,%2,%3}, {%4,%5,%6,%7}, {%8,%9}, {%0,%1,%2,%3};"
        : "+f"(c[0]), "+f"(c[1]), "+f"(c[2]), "+f"(c[3])
        : "r"(a0), "r"(a1), "r"(a2), "r"(a3), "r"(b0), "r"(b1));
}
__device__ __forceinline__ void cpasync16(u32 dst, const void* src) {
    asm volatile("cp.async.cg.shared.global [%0], [%1], 16;"
                 :: "r"(dst), "l"(src) : "memory");
}

// ---------------------------------------------------------------------------
// Pre-pass 1: dequantize weights -> fp16, packed [ch][tap][half][ocl][k]
// ---------------------------------------------------------------------------
__global__ void dequant_wh(const int* __restrict__ q,
                           const float* __restrict__ sc,
                           const float* __restrict__ mn) {
    int i = blockIdx.x * 256 + threadIdx.x;
    if (i >= NCH * 9 * 2 * 128 * 16) return;
    float s = *sc, m = *mn;
    int ch = i / 36864, r = i % 36864;
    int tap = r / 4096, r2 = r % 4096;
    int hf = r2 / 2048, r3 = r2 % 2048;
    int ocl = r3 / 16, k = r3 % 16;
    int oc = hf * 128 + ocl, cin = ch * 16 + k;
    g_wh[i] = __float2half((float)q[(oc * CIN_ + cin) * 9 + tap] * s + m);
}

// ---------------------------------------------------------------------------
// Pre-pass 2: x -> fp16, chunk-major padded 64-pitch slabs with guards.
// ---------------------------------------------------------------------------
__global__ void pack_x(const float* __restrict__ x) {
    u32 i = blockIdx.x * 256 + threadIdx.x;
    if (i >= (u32)NIMG * NCH * 3840) return;
    u32 pg = i % 3840, nc = i / 3840;       // nc = n*16 + ch
    int g = (int)pg - 128;
    int row = g >> 6, col = g & 63;
    bool ok = (g >= 0) && (row < HW_) && (col < HW_);
    __align__(16) __half hv[16];
#pragma unroll
    for (int ck = 0; ck < 16; ck++) {
        float v = 0.0f;
        if (ok) v = x[((u64)nc * 16 + ck) * (HW_ * HW_) + row * HW_ + col];
        hv[ck] = __float2half(v);
    }
    u64 o = ((u64)nc * 3840 + pg) * 16;
    *(uint4*)(g_xh + o)     = *(uint4*)hv;
    *(uint4*)(g_xh + o + 8) = *(uint4*)(hv + 8);
}

// ---------------------------------------------------------------------------
// Conv: HMMA implicit conv, 16 warps, 3-stage cp.async pipeline.
// grid = (2 oc-halves, 28 row-pairs, 32 imgs), block = 512.
// CTA tile M=128 px x N=128 oc; warp tile 32x32; single fp16 term.
// ---------------------------------------------------------------------------
extern __shared__ char smem[];
__global__ void __launch_bounds__(512, 1)
conv_hmma(const float* __restrict__ bias, float* __restrict__ out) {
    const u32 sb = smem_u32(smem);
    const int tid = threadIdx.x, wid = tid >> 5, lane = tid & 31;
    const int half_ = blockIdx.x, rp = blockIdx.y, n = blockIdx.z;
    const int r0 = rp * 2, oc0 = half_ * 128;
    const int warp_m = wid & 3, warp_n = wid >> 2;

    float* s_bias = (float*)(smem + SM_BIAS);
    if (tid < 128) s_bias[tid] = bias[oc0 + tid];

    float acc[2][4][4];
#pragma unroll
    for (int a = 0; a < 2; a++)
#pragma unroll
        for (int b = 0; b < 4; b++)
#pragma unroll
            for (int c = 0; c < 4; c++) acc[a][b][c] = 0.0f;

    const u32 abase_pix = (u32)(r0 * 64 + 56);   // slab index of staged row 0
    const int a_row = lane & 15, a_seg = lane >> 4;
    const int b_row = (lane & 7) + ((lane >> 4) << 3), b_seg = (lane >> 3) & 1;

    auto prefetch = [&](int ch) {
        int s = ch % 3;
        u32 aH = sb + s * ST_SZ, bB = aH + ST_A;
        const __half* srcH = g_xh + ((u64)(n * NCH + ch) * 3840 + abase_pix) * 16;
        for (int i = tid; i < 544; i += 512) {            // 272 rows x 2 halves
            int qs = i >> 1, h = i & 1;
            cpasync16(aH + qs * 48 + h * 16, srcH + qs * 16 + h * 8);
        }
        for (int i = tid; i < 2304; i += 512) {           // 9 taps x 128 ocl x 2
            int tap = i / 256, r = i & 255, ocl = r >> 1, h = r & 1;
            const __half* sBp = g_wh +
                (u64)((ch * 9 + tap) * 2 + half_) * 2048 + ocl * 16 + h * 8;
            cpasync16(bB + tap * 6144 + ocl * 48 + h * 16, sBp);
        }
        asm volatile("cp.async.commit_group;" ::: "memory");
    };

    prefetch(0);
    prefetch(1);
    prefetch(2);

    for (int ch = 0; ch < NCH; ch++) {
        const int rem = NCH - 1 - ch;
        if (rem >= 2)
            asm volatile("cp.async.wait_group 2;" ::: "memory");
        else if (rem == 1)
            asm volatile("cp.async.wait_group 1;" ::: "memory");
        else
            asm volatile("cp.async.wait_group 0;" ::: "memory");
        __syncthreads();

        const int s = ch % 3;
        const u32 aH = sb + s * ST_SZ, bB = aH + ST_A;
#pragma unroll 1
        for (int tap = 0; tap < 9; tap++) {
            const int kh = tap / 3, kwp = tap - kh * 3 + 7;
            u32 bf[8];
            u32 bb = bB + tap * 6144 + warp_n * 1536;
            ldsm4(bf[0], bf[1], bf[2], bf[3], bb + b_row * 48 + b_seg * 16);
            ldsm4(bf[4], bf[5], bf[6], bf[7], bb + (16 + b_row) * 48 + b_seg * 16);
#pragma unroll
            for (int mt = 0; mt < 2; mt++) {
                int qs = warp_m * 32 + mt * 16 + kh * 64 + kwp + a_row;
                u32 a0, a1, a2, a3;
                ldsm4(a0, a1, a2, a3, aH + qs * 48 + a_seg * 16);
#pragma unroll
                for (int nt = 0; nt < 4; nt++)
                    mma16816(acc[mt][nt], a0, a1, a2, a3, bf[nt * 2], bf[nt * 2 + 1]);
            }
        }
        __syncthreads();
        if (ch + 3 < NCH) prefetch(ch + 3);
    }

    // epilogue: frags -> smem transpose -> coalesced gmem + bias
    float* scf = (float*)smem;     // [128 oc][130 px]
#pragma unroll
    for (int mt = 0; mt < 2; mt++)
#pragma unroll
        for (int nt = 0; nt < 4; nt++) {
            int px = warp_m * 32 + mt * 16 + (lane >> 2);
            int ocl = warp_n * 32 + nt * 8 + (lane & 3) * 2;
            scf[ocl * 130 + px]           = acc[mt][nt][0];
            scf[(ocl + 1) * 130 + px]     = acc[mt][nt][1];
            scf[ocl * 130 + px + 8]       = acc[mt][nt][2];
            scf[(ocl + 1) * 130 + px + 8] = acc[mt][nt][3];
        }
    __syncthreads();

    for (int i = tid; i < 128 * 112; i += 512) {
        int ocl = i / 112, p = i % 112;
        int orow = p / 56, ow = p % 56;
        int px = orow * 64 + ow;
        out[((u64)(n * OC_ + oc0 + ocl) * HW_ + (r0 + orow)) * HW_ + ow] =
            scf[ocl * 130 + px] + s_bias[ocl];
    }
}

// ---------------------------------------------------------------------------
// Launch: inputs: x, q_weight, w_scale, w_min, bias
// ---------------------------------------------------------------------------
extern "C" void kernel_launch(void* const* d_in, const int* in_sizes, int n_in,
                              void* d_out, int out_size) {
    const float* x    = (const float*)d_in[0];
    const int*   q    = (const int*)  d_in[1];
    const float* ws   = (const float*)d_in[2];
    const float* wm   = (const float*)d_in[3];
    const float* bias = (const float*)d_in[4];
    float* out = (float*)d_out;
    (void)in_sizes; (void)n_in; (void)out_size;

    cudaFuncSetAttribute(conv_hmma, cudaFuncAttributeMaxDynamicSharedMemorySize, SM_TOT);

    dequant_wh<<<(NCH * 9 * 2 * 128 * 16 + 255) / 256, 256>>>(q, ws, wm);
    pack_x<<<((u32)NIMG * NCH * 3840 + 255) / 256, 256>>>(x);

    dim3 grid(2, 28, NIMG);
    conv_hmma<<<grid, 512, SM_TOT>>>(bias, out);
}

// round 17
// speedup vs baseline: 5.1242x; 1.3101x over previous
#include <cuda_runtime.h>
#include <cuda_fp16.h>

typedef unsigned long long u64;
typedef unsigned int u32;

#define HW_   56
#define CIN_  256
#define OC_   256
#define NIMG  32
#define NCH   16

// smem: three stages of (A | B), then bias
#define ST_A   19200               // 400 rows * 48B
#define ST_B   55296               // 9 taps * 128 ocl * 48B
#define ST_SZ  (ST_A + ST_B)       // 74496
#define SM_BIAS (3 * ST_SZ)        // 223488
#define SM_TOT  (SM_BIAS + 512)    // 224000
// epilogue reuses [0, 133120) as C[128 oc][260 px] f32

// fp16 weights: [ch][tap][half][ocl][k16]
__device__ __align__(16) __half g_wh[NCH * 9 * 2 * 128 * 16];
// x packed fp16 per (n, ch): [3840 padded pixels][16 ck]
// pixel slab: 128 guard + 3584 (56 rows * 64 pitch) + 128 guard
__device__ __align__(16) __half g_xh[(u64)NIMG * NCH * 3840 * 16];

__device__ __forceinline__ u32 smem_u32(const void* p) {
    u32 a;
    asm("{ .reg .u64 t; cvta.to.shared.u64 t, %1; cvt.u32.u64 %0, t; }"
        : "=r"(a) : "l"(p));
    return a;
}
__device__ __forceinline__ void ldsm4(u32& r0, u32& r1, u32& r2, u32& r3, u32 addr) {
    asm volatile("ldmatrix.sync.aligned.m8n8.x4.shared.b16 {%0,%1,%2,%3}, [%4];"
                 : "=r"(r0), "=r"(r1), "=r"(r2), "=r"(r3) : "r"(addr));
}
__device__ __forceinline__ void mma16816(float* c, u32 a0, u32 a1, u32 a2, u32 a3,
                                         u32 b0, u32 b1) {
    asm volatile(
        "mma.sync.aligned.m16n8k16.row.col.f32.f16.f16.f32 "
        "{%0,%1,%2,%3}, {%4,%5,%6,%7}, {%8,%9}, {%0,%1,%2,%3};"
        : "+f"(c[0]), "+f"(c[1]), "+f"(c[2]), "+f"(c[3])
        : "r"(a0), "r"(a1), "r"(a2), "r"(a3), "r"(b0), "r"(b1));
}
__device__ __forceinline__ void cpasync16(u32 dst, const void* src) {
    asm volatile("cp.async.cg.shared.global [%0], [%1], 16;"
                 :: "r"(dst), "l"(src) : "memory");
}

// ---------------------------------------------------------------------------
// Pre-pass 1: dequantize weights -> fp16, packed [ch][tap][half][ocl][k]
// ---------------------------------------------------------------------------
__global__ void dequant_wh(const int* __restrict__ q,
                           const float* __restrict__ sc,
                           const float* __restrict__ mn) {
    int i = blockIdx.x * 256 + threadIdx.x;
    if (i >= NCH * 9 * 2 * 128 * 16) return;
    float s = *sc, m = *mn;
    int ch = i / 36864, r = i % 36864;
    int tap = r / 4096, r2 = r % 4096;
    int hf = r2 / 2048, r3 = r2 % 2048;
    int ocl = r3 / 16, k = r3 % 16;
    int oc = hf * 128 + ocl, cin = ch * 16 + k;
    g_wh[i] = __float2half((float)q[(oc * CIN_ + cin) * 9 + tap] * s + m);
}

// ---------------------------------------------------------------------------
// Pre-pass 2: x -> fp16, chunk-major padded 64-pitch slabs with guards.
// ---------------------------------------------------------------------------
__global__ void pack_x(const float* __restrict__ x) {
    u32 i = blockIdx.x * 256 + threadIdx.x;
    if (i >= (u32)NIMG * NCH * 3840) return;
    u32 pg = i % 3840, nc = i / 3840;       // nc = n*16 + ch
    int g = (int)pg - 128;
    int row = g >> 6, col = g & 63;
    bool ok = (g >= 0) && (row < HW_) && (col < HW_);
    __align__(16) __half hv[16];
#pragma unroll
    for (int ck = 0; ck < 16; ck++) {
        float v = 0.0f;
        if (ok) v = x[((u64)nc * 16 + ck) * (HW_ * HW_) + row * HW_ + col];
        hv[ck] = __float2half(v);
    }
    u64 o = ((u64)nc * 3840 + pg) * 16;
    *(uint4*)(g_xh + o)     = *(uint4*)hv;
    *(uint4*)(g_xh + o + 8) = *(uint4*)(hv + 8);
}

// ---------------------------------------------------------------------------
// Conv: HMMA implicit conv, 16 warps, 3-stage cp.async pipeline.
// grid = (2 oc-halves, 14 row-quads, 32 imgs), block = 512.
// CTA tile M=256 px (4 rows x 64-pitch) x N=128 oc; warp tile 64x32.
// ---------------------------------------------------------------------------
extern __shared__ char smem[];
__global__ void __launch_bounds__(512, 1)
conv_hmma(const float* __restrict__ bias, float* __restrict__ out) {
    const u32 sb = smem_u32(smem);
    const int tid = threadIdx.x, wid = tid >> 5, lane = tid & 31;
    const int half_ = blockIdx.x, rp = blockIdx.y, n = blockIdx.z;
    const int r0 = rp * 4, oc0 = half_ * 128;
    const int warp_m = wid & 3, warp_n = wid >> 2;

    float* s_bias = (float*)(smem + SM_BIAS);
    if (tid < 128) s_bias[tid] = bias[oc0 + tid];

    float acc[4][4][4];
#pragma unroll
    for (int a = 0; a < 4; a++)
#pragma unroll
        for (int b = 0; b < 4; b++)
#pragma unroll
            for (int c = 0; c < 4; c++) acc[a][b][c] = 0.0f;

    const u32 abase_pix = (u32)(r0 * 64 + 56);   // slab index of staged row 0
    const int a_row = lane & 15, a_seg = lane >> 4;
    const int b_row = (lane & 7) + ((lane >> 4) << 3), b_seg = (lane >> 3) & 1;

    auto prefetch = [&](int ch) {
        int s = ch % 3;
        u32 aH = sb + s * ST_SZ, bB = aH + ST_A;
        const __half* srcH = g_xh + ((u64)(n * NCH + ch) * 3840 + abase_pix) * 16;
        for (int i = tid; i < 800; i += 512) {            // 400 rows x 2 halves
            int qs = i >> 1, h = i & 1;
            cpasync16(aH + qs * 48 + h * 16, srcH + qs * 16 + h * 8);
        }
        for (int i = tid; i < 2304; i += 512) {           // 9 taps x 128 ocl x 2
            int tap = i / 256, r = i & 255, ocl = r >> 1, h = r & 1;
            const __half* sBp = g_wh +
                (u64)((ch * 9 + tap) * 2 + half_) * 2048 + ocl * 16 + h * 8;
            cpasync16(bB + tap * 6144 + ocl * 48 + h * 16, sBp);
        }
        asm volatile("cp.async.commit_group;" ::: "memory");
    };

    prefetch(0);
    prefetch(1);
    prefetch(2);

    for (int ch = 0; ch < NCH; ch++) {
        const int rem = NCH - 1 - ch;
        if (rem >= 2)
            asm volatile("cp.async.wait_group 2;" ::: "memory");
        else if (rem == 1)
            asm volatile("cp.async.wait_group 1;" ::: "memory");
        else
            asm volatile("cp.async.wait_group 0;" ::: "memory");
        __syncthreads();

        const int s = ch % 3;
        const u32 aH = sb + s * ST_SZ, bB = aH + ST_A;
#pragma unroll 1
        for (int tap = 0; tap < 9; tap++) {
            const int kh = tap / 3, kwp = tap - kh * 3 + 7;
            u32 bf[8];
            u32 bb = bB + tap * 6144 + warp_n * 1536;
            ldsm4(bf[0], bf[1], bf[2], bf[3], bb + b_row * 48 + b_seg * 16);
            ldsm4(bf[4], bf[5], bf[6], bf[7], bb + (16 + b_row) * 48 + b_seg * 16);
#pragma unroll
            for (int mt = 0; mt < 4; mt++) {
                int qs = warp_m * 64 + mt * 16 + kh * 64 + kwp + a_row;
                u32 a0, a1, a2, a3;
                ldsm4(a0, a1, a2, a3, aH + qs * 48 + a_seg * 16);
#pragma unroll
                for (int nt = 0; nt < 4; nt++)
                    mma16816(acc[mt][nt], a0, a1, a2, a3, bf[nt * 2], bf[nt * 2 + 1]);
            }
        }
        __syncthreads();
        if (ch + 3 < NCH) prefetch(ch + 3);
    }

    // epilogue: frags -> smem transpose -> coalesced gmem + bias
    float* scf = (float*)smem;     // [128 oc][260 px]
#pragma unroll
    for (int mt = 0; mt < 4; mt++)
#pragma unroll
        for (int nt = 0; nt < 4; nt++) {
            int px = warp_m * 64 + mt * 16 + (lane >> 2);
            int ocl = warp_n * 32 + nt * 8 + (lane & 3) * 2;
            scf[ocl * 260 + px]           = acc[mt][nt][0];
            scf[(ocl + 1) * 260 + px]     = acc[mt][nt][1];
            scf[ocl * 260 + px + 8]       = acc[mt][nt][2];
            scf[(ocl + 1) * 260 + px + 8] = acc[mt][nt][3];
        }
    __syncthreads();

    for (int i = tid; i < 128 * 224; i += 512) {
        int ocl = i / 224, p = i % 224;
        int orow = p / 56, ow = p % 56;
        int px = orow * 64 + ow;
        out[((u64)(n * OC_ + oc0 + ocl) * HW_ + (r0 + orow)) * HW_ + ow] =
            scf[ocl * 260 + px] + s_bias[ocl];
    }
}

// ---------------------------------------------------------------------------
// Launch: inputs: x, q_weight, w_scale, w_min, bias
// ---------------------------------------------------------------------------
extern "C" void kernel_launch(void* const* d_in, const int* in_sizes, int n_in,
                              void* d_out, int out_size) {
    const float* x    = (const float*)d_in[0];
    const int*   q    = (const int*)  d_in[1];
    const float* ws   = (const float*)d_in[2];
    const float* wm   = (const float*)d_in[3];
    const float* bias = (const float*)d_in[4];
    float* out = (float*)d_out;
    (void)in_sizes; (void)n_in; (void)out_size;

    cudaFuncSetAttribute(conv_hmma, cudaFuncAttributeMaxDynamicSharedMemorySize, SM_TOT);

    dequant_wh<<<(NCH * 9 * 2 * 128 * 16 + 255) / 256, 256>>>(q, ws, wm);
    pack_x<<<((u32)NIMG * NCH * 3840 + 255) / 256, 256>>>(x);

    dim3 grid(2, 14, NIMG);
    conv_hmma<<<grid, 512, SM_TOT>>>(bias, out);
}